// round 1
// baseline (speedup 1.0000x reference)
#include <cuda_runtime.h>

// Problem dims (fixed by the dataset)
#define BB 8192      // batch
#define IND 19000    // input dim
#define SD 256       // shared dim
#define PDD 128      // pathway dim
#define PP 16        // n pathways
#define DD 64        // n drugs

// Scratch for h = relu(x@W1+b1): 8192*256 floats = 8 MB (device global, no alloc)
__device__ float g_h[(size_t)BB * SD];

// ---------------------------------------------------------------------------
// Kernel 1: h = relu(x @ W1 + b1)
// M=8192, K=19000, N=256. Tile: BM=64, BN=128, BK=8. 256 threads, TM=4, TN=8.
// Grid: (8192/64, 256/128) = (128, 2) = 256 blocks, ~1.7/SM.
// ---------------------------------------------------------------------------
__global__ __launch_bounds__(256, 2)
void gemm1_relu_kernel(const float* __restrict__ x,
                       const float* __restrict__ W1,
                       const float* __restrict__ b1)
{
    __shared__ float As[8][64];    // transposed: As[k][m]
    __shared__ float Bs[8][128];   // Bs[k][n]

    const int tid = threadIdx.x;
    const int row0 = blockIdx.x * 64;
    const int col0 = blockIdx.y * 128;

    const int tx = tid & 15;       // N group (×8)
    const int ty = tid >> 4;       // M group (×4)

    float acc[4][8];
#pragma unroll
    for (int i = 0; i < 4; i++)
#pragma unroll
        for (int j = 0; j < 8; j++) acc[i][j] = 0.f;

    // A-tile load mapping: 64 rows x 8 cols = 512 floats, 256 threads -> float2 each
    const int la_row = tid >> 2;          // 0..63
    const int la_k   = (tid & 3) * 2;     // 0,2,4,6
    const float* xp = x + (size_t)(row0 + la_row) * IND + la_k;

    // B-tile load mapping: 8 rows x 128 cols = 1024 floats -> float4 each
    const int lb_k = tid >> 5;            // 0..7
    const int lb_c = (tid & 31) * 4;      // 0..124
    const float* wp = W1 + (size_t)lb_k * SD + col0 + lb_c;

    for (int k0 = 0; k0 < IND; k0 += 8) {
        // issue global loads early
        float2 av = *(const float2*)(xp + k0);
        float4 bv = *(const float4*)(wp + (size_t)k0 * SD);

        __syncthreads();   // previous compute done before overwrite
        As[la_k    ][la_row] = av.x;
        As[la_k + 1][la_row] = av.y;
        *(float4*)&Bs[lb_k][lb_c] = bv;
        __syncthreads();

#pragma unroll
        for (int k = 0; k < 8; k++) {
            float4 a  = *(const float4*)&As[k][ty * 4];
            float4 b0 = *(const float4*)&Bs[k][tx * 8];
            float4 b1v = *(const float4*)&Bs[k][tx * 8 + 4];
            float ar[4] = {a.x, a.y, a.z, a.w};
            float br[8] = {b0.x, b0.y, b0.z, b0.w, b1v.x, b1v.y, b1v.z, b1v.w};
#pragma unroll
            for (int i = 0; i < 4; i++)
#pragma unroll
                for (int j = 0; j < 8; j++)
                    acc[i][j] = fmaf(ar[i], br[j], acc[i][j]);
        }
    }

    // epilogue: bias + relu -> g_h
#pragma unroll
    for (int i = 0; i < 4; i++) {
        int row = row0 + ty * 4 + i;
#pragma unroll
        for (int j = 0; j < 8; j++) {
            int col = col0 + tx * 8 + j;
            float v = acc[i][j] + __ldg(&b1[col]);
            g_h[(size_t)row * SD + col] = fmaxf(v, 0.f);
        }
    }
}

// ---------------------------------------------------------------------------
// Kernel 2: per-sample pathway expert + drug head.
//   pw = relu(h_row @ Wp[p] + bp[p]);  out = dot(pw, Wd[drug]) + bd[drug]
// One block (128 threads) per sample; thread d owns output column d.
// Wp working set = 16*256*128*4 = 2 MB -> L2 resident.
// ---------------------------------------------------------------------------
__global__ __launch_bounds__(128)
void pathway_drug_kernel(const float* __restrict__ Wp,
                         const float* __restrict__ bp,
                         const float* __restrict__ Wd,
                         const float* __restrict__ bd,
                         const int*   __restrict__ drug_indices,
                         const int*   __restrict__ drug_to_pw,
                         float*       __restrict__ out)
{
    const int b   = blockIdx.x;
    const int tid = threadIdx.x;   // 0..127 = pathway-dim column

    __shared__ float hs[SD];
    __shared__ float red[4];

    const int drug = drug_indices[b];
    const int p    = drug_to_pw[drug];

    hs[tid]       = g_h[(size_t)b * SD + tid];
    hs[tid + 128] = g_h[(size_t)b * SD + tid + 128];
    __syncthreads();

    const float* wcol = Wp + (size_t)p * SD * PDD + tid;  // stride PDD over s
    float acc = 0.f;
#pragma unroll 8
    for (int s = 0; s < SD; s++)
        acc = fmaf(hs[s], wcol[(size_t)s * PDD], acc);

    acc += bp[p * PDD + tid];
    acc = fmaxf(acc, 0.f);

    float v = acc * Wd[drug * PDD + tid];
    // block reduce over 128 lanes
#pragma unroll
    for (int off = 16; off > 0; off >>= 1)
        v += __shfl_xor_sync(0xffffffffu, v, off);
    if ((tid & 31) == 0) red[tid >> 5] = v;
    __syncthreads();
    if (tid == 0)
        out[b] = red[0] + red[1] + red[2] + red[3] + bd[drug];
}

// ---------------------------------------------------------------------------
// Launch
// Inputs (metadata order): x, drug_indices, W1, b1, Wp, bp, Wd, bd, drug_to_pw
// ---------------------------------------------------------------------------
extern "C" void kernel_launch(void* const* d_in, const int* in_sizes, int n_in,
                              void* d_out, int out_size)
{
    const float* x            = (const float*)d_in[0];
    const int*   drug_indices = (const int*)  d_in[1];
    const float* W1           = (const float*)d_in[2];
    const float* b1           = (const float*)d_in[3];
    const float* Wp           = (const float*)d_in[4];
    const float* bp           = (const float*)d_in[5];
    const float* Wd           = (const float*)d_in[6];
    const float* bd           = (const float*)d_in[7];
    const int*   drug_to_pw   = (const int*)  d_in[8];
    float*       out          = (float*)d_out;

    dim3 grid1(BB / 64, SD / 128);
    gemm1_relu_kernel<<<grid1, 256>>>(x, W1, b1);

    pathway_drug_kernel<<<BB, 128>>>(Wp, bp, Wd, bd, drug_indices, drug_to_pw, out);
}

// round 3
// speedup vs baseline: 6.4383x; 6.4383x over previous
#include <cuda_runtime.h>
#include <cstdint>

// ---------------------------------------------------------------------------
// Problem dims
// ---------------------------------------------------------------------------
#define BB   8192
#define KTOT 19000
#define SD   256
#define PDD  128
#define PP   16
#define DD   64

#define BM 128
#define BN 256
#define BK 32
#define KHALF 9500           // split-K=2: each half is 9500 (mult of 4)
#define NTILES 297           // ceil(9500/32)
#define STAGES 3

// smem strides (floats) chosen for conflict-free frag reads
#define A_STRIDE 36          // 128 rows x 36
#define B_STRIDE 264         // 32 rows x 264
#define STAGE_A_BYTES (BM * A_STRIDE * 4)        // 18432
#define STAGE_B_BYTES (BK * B_STRIDE * 4)        // 33792
#define STAGE_BYTES   (STAGE_A_BYTES + STAGE_B_BYTES)  // 52224
#define SMEM_TOTAL    (STAGES * STAGE_BYTES)     // 156672

// Scratch (device globals; no allocation allowed)
__device__ float g_h_a[(size_t)BB * SD];   // split 0 partial (+bias)
__device__ float g_h_b[(size_t)BB * SD];   // split 1 partial

// ---------------------------------------------------------------------------
// helpers
// ---------------------------------------------------------------------------
__device__ __forceinline__ uint32_t smem_u32(const void* p) {
    uint32_t a;
    asm("{ .reg .u64 t; cvta.to.shared.u64 t, %1; cvt.u32.u64 %0, t; }" : "=r"(a) : "l"(p));
    return a;
}
__device__ __forceinline__ uint32_t cvt_tf32(float f) {
    uint32_t r;
    asm("cvt.rn.tf32.f32 %0, %1;" : "=r"(r) : "f"(f));
    return r;
}
__device__ __forceinline__ void cp_async16(uint32_t dst, const void* src, bool valid) {
    int sz = valid ? 16 : 0;
    asm volatile("cp.async.cg.shared.global [%0], [%1], 16, %2;\n"
                 :: "r"(dst), "l"(src), "r"(sz));
}
#define CP_COMMIT() asm volatile("cp.async.commit_group;" ::: "memory")
#define CP_WAIT1()  asm volatile("cp.async.wait_group 1;" ::: "memory")

__device__ __forceinline__ void mma_tf32(float* c, const uint32_t* a, const uint32_t* b) {
    asm volatile(
        "mma.sync.aligned.m16n8k8.row.col.f32.tf32.tf32.f32 "
        "{%0,%1,%2,%3}, {%4,%5,%6,%7}, {%8,%9}, {%0,%1,%2,%3};"
        : "+f"(c[0]), "+f"(c[1]), "+f"(c[2]), "+f"(c[3])
        : "r"(a[0]), "r"(a[1]), "r"(a[2]), "r"(a[3]), "r"(b[0]), "r"(b[1]));
}

// ---------------------------------------------------------------------------
// Kernel 1: h_partial = x @ W1 (tf32 mma.sync), split-K=2, bias on split 0.
// grid (64, 2), 512 threads (16 warps, 4x4), warp tile 32x64.
// ---------------------------------------------------------------------------
__global__ __launch_bounds__(512, 1)
void gemm_tf32_kernel(const float* __restrict__ x,
                      const float* __restrict__ W1,
                      const float* __restrict__ b1)
{
    extern __shared__ char smem[];
    const uint32_t sb = smem_u32(smem);

    const int tid  = threadIdx.x;
    const int wid  = tid >> 5;
    const int lane = tid & 31;
    const int wm   = wid & 3;           // warp m index (0..3)
    const int wn   = wid >> 2;          // warp n index (0..3)
    const int m0   = blockIdx.x * BM;
    const int ky   = blockIdx.y;
    const int kstart = ky * KHALF;
    const int kend   = kstart + KHALF;

    // ---- load mappings (16B segments) ----
    // A: 1024 segs: row = seg>>3 (0..127), kseg = seg&7
    const int a_row  = (tid >> 3) | 0;           // seg = tid + i*512
    // B: 2048 segs: row = seg>>6 (0..31), nseg = seg&63
    // (computed inline per i)

    float acc[2][8][4];
#pragma unroll
    for (int mi = 0; mi < 2; mi++)
#pragma unroll
        for (int ni = 0; ni < 8; ni++)
#pragma unroll
            for (int j = 0; j < 4; j++) acc[mi][ni][j] = 0.f;

    // ---- tile loader ----
    auto load_tile = [&](int t, int stage) {
        const int kb = kstart + t * BK;
        const uint32_t abase = sb + stage * STAGE_BYTES;
        const uint32_t bbase = abase + STAGE_A_BYTES;
#pragma unroll
        for (int i = 0; i < 2; i++) {
            int seg = tid + i * 512;             // 0..1023
            int row = seg >> 3;
            int ks  = (seg & 7) << 2;            // k offset in floats
            int kg  = kb + ks;
            cp_async16(abase + row * (A_STRIDE * 4) + ks * 4,
                       x + (size_t)(m0 + row) * KTOT + kg,
                       kg < kend);
        }
#pragma unroll
        for (int i = 0; i < 4; i++) {
            int seg = tid + i * 512;             // 0..2047
            int row = seg >> 6;                  // k row 0..31
            int ns  = (seg & 63) << 2;           // n offset in floats
            int kg  = kb + row;
            cp_async16(bbase + row * (B_STRIDE * 4) + ns * 4,
                       W1 + (size_t)kg * SD + ns,
                       kg < kend);
        }
    };

    // prologue
#pragma unroll
    for (int s = 0; s < STAGES - 1; s++) { load_tile(s, s); CP_COMMIT(); }

    const int wrow = wm * 32;           // warp row base within tile
    const int wcol = wn * 64;           // warp col base within tile

    for (int t = 0; t < NTILES; t++) {
        CP_WAIT1();
        __syncthreads();

        int tn = t + STAGES - 1;
        if (tn < NTILES) load_tile(tn, tn % STAGES);
        CP_COMMIT();

        const int stage = t % STAGES;
        const float* As = (const float*)(smem + stage * STAGE_BYTES);
        const float* Bs = (const float*)(smem + stage * STAGE_BYTES + STAGE_A_BYTES);

#pragma unroll
        for (int ks = 0; ks < 4; ks++) {
            const int k0 = ks * 8;
            uint32_t a[2][4];
#pragma unroll
            for (int mi = 0; mi < 2; mi++) {
                int r = wrow + mi * 16 + (lane >> 2);
                int c = k0 + (lane & 3);
                a[mi][0] = cvt_tf32(As[(r    ) * A_STRIDE + c    ]);
                a[mi][1] = cvt_tf32(As[(r + 8) * A_STRIDE + c    ]);
                a[mi][2] = cvt_tf32(As[(r    ) * A_STRIDE + c + 4]);
                a[mi][3] = cvt_tf32(As[(r + 8) * A_STRIDE + c + 4]);
            }
            uint32_t b[8][2];
#pragma unroll
            for (int ni = 0; ni < 8; ni++) {
                int kr = k0 + (lane & 3);
                int c  = wcol + ni * 8 + (lane >> 2);
                b[ni][0] = cvt_tf32(Bs[(kr    ) * B_STRIDE + c]);
                b[ni][1] = cvt_tf32(Bs[(kr + 4) * B_STRIDE + c]);
            }
#pragma unroll
            for (int mi = 0; mi < 2; mi++)
#pragma unroll
                for (int ni = 0; ni < 8; ni++)
                    mma_tf32(acc[mi][ni], a[mi], b[ni]);
        }
        __syncthreads();
    }

    // ---- epilogue: write partial h (bias on split 0) ----
    float* outp = (ky == 0) ? g_h_a : g_h_b;
#pragma unroll
    for (int mi = 0; mi < 2; mi++) {
        int r0 = m0 + wrow + mi * 16 + (lane >> 2);
#pragma unroll
        for (int ni = 0; ni < 8; ni++) {
            int c = wcol + ni * 8 + (lane & 3) * 2;
            float bx = 0.f, by = 0.f;
            if (ky == 0) { bx = __ldg(&b1[c]); by = __ldg(&b1[c + 1]); }
            float2 v0 = make_float2(acc[mi][ni][0] + bx, acc[mi][ni][1] + by);
            float2 v1 = make_float2(acc[mi][ni][2] + bx, acc[mi][ni][3] + by);
            *(float2*)(outp + (size_t)r0 * SD + c)       = v0;
            *(float2*)(outp + (size_t)(r0 + 8) * SD + c) = v1;
        }
    }
}

// ---------------------------------------------------------------------------
// Kernel 2: per-sample pathway expert + drug head.
//   h = relu(g_h_a + g_h_b); pw = relu(h @ Wp[p] + bp[p]); out = pw.Wd[drug]+bd
// ---------------------------------------------------------------------------
__global__ __launch_bounds__(128)
void pathway_drug_kernel(const float* __restrict__ Wp,
                         const float* __restrict__ bp,
                         const float* __restrict__ Wd,
                         const float* __restrict__ bd,
                         const int*   __restrict__ drug_indices,
                         const int*   __restrict__ drug_to_pw,
                         float*       __restrict__ out)
{
    const int b   = blockIdx.x;
    const int tid = threadIdx.x;

    __shared__ float hs[SD];
    __shared__ float red[4];

    const int drug = drug_indices[b];
    const int p    = drug_to_pw[drug];

    {
        size_t i0 = (size_t)b * SD + tid;
        hs[tid]       = fmaxf(g_h_a[i0]       + g_h_b[i0],       0.f);
        hs[tid + 128] = fmaxf(g_h_a[i0 + 128] + g_h_b[i0 + 128], 0.f);
    }
    __syncthreads();

    const float* wcol = Wp + (size_t)p * SD * PDD + tid;
    float acc = 0.f;
#pragma unroll 8
    for (int s = 0; s < SD; s++)
        acc = fmaf(hs[s], wcol[(size_t)s * PDD], acc);

    acc += bp[p * PDD + tid];
    acc = fmaxf(acc, 0.f);

    float v = acc * Wd[drug * PDD + tid];
#pragma unroll
    for (int off = 16; off > 0; off >>= 1)
        v += __shfl_xor_sync(0xffffffffu, v, off);
    if ((tid & 31) == 0) red[tid >> 5] = v;
    __syncthreads();
    if (tid == 0)
        out[b] = red[0] + red[1] + red[2] + red[3] + bd[drug];
}

// ---------------------------------------------------------------------------
// Launch. Inputs: x, drug_indices, W1, b1, Wp, bp, Wd, bd, drug_to_pw
// ---------------------------------------------------------------------------
extern "C" void kernel_launch(void* const* d_in, const int* in_sizes, int n_in,
                              void* d_out, int out_size)
{
    const float* x            = (const float*)d_in[0];
    const int*   drug_indices = (const int*)  d_in[1];
    const float* W1           = (const float*)d_in[2];
    const float* b1           = (const float*)d_in[3];
    const float* Wp           = (const float*)d_in[4];
    const float* bp           = (const float*)d_in[5];
    const float* Wd           = (const float*)d_in[6];
    const float* bd           = (const float*)d_in[7];
    const int*   drug_to_pw   = (const int*)  d_in[8];
    float*       out          = (float*)d_out;

    static int smem_set = 0;
    if (!smem_set) {
        cudaFuncSetAttribute(gemm_tf32_kernel,
                             cudaFuncAttributeMaxDynamicSharedMemorySize, SMEM_TOTAL);
        smem_set = 1;
    }

    dim3 ggrid(BB / BM, 2);
    gemm_tf32_kernel<<<ggrid, 512, SMEM_TOTAL>>>(x, W1, b1);

    pathway_drug_kernel<<<BB, 128>>>(Wp, bp, Wd, bd, drug_indices, drug_to_pw, out);
}